// round 11
// baseline (speedup 1.0000x reference)
#include <cuda_runtime.h>
#include <cstdint>

// ============================================================================
// out[16384,4096] = x @ ((W_int - zp)*scale)^T + bias       (sm_103, no tcgen05)
// int8 IMMA (mma.sync.m16n8k32.s8) with 2-slice fixed-point decomposition:
//   s1 = rowmax|x|/127; q1 = rint(x/s1); q2 = rint((x - s1 q1)/(s1/254))
//   gemm = (s1/254) * (254*d1 + d2)   with d1,d2 exact int32 dot products.
//   Single int accumulator: run slice1, acc *= 254, run slice2 on top.
// W ints cast to int8 exactly. Epilogue: out = scale*gemm - (scale*zp)*rowsum + bias.
// Same proven SMEM swizzle + ldmatrix addressing as tf32 R9 kernel (byte-identical),
// but each 128B SMEM row now holds K=128 int8 -> half the iters, half bytes/MAC.
// (R10 resubmission: fixed signed char* / const char* type mismatch.)
// ============================================================================

#define M_TOTAL 16384
#define N_TOTAL 4096
#define K_TOTAL 4096
#define BM 128
#define BN 128
#define BKB 128                        // K-bytes per iter (128 int8)
#define NST 3
#define HALF_ITERS 32                  // 4096 / 128
#define NITERS 64                      // 2 slices
#define ASTAGE 16384                   // 128 rows x 128B
#define SMEM_BYTES (NST * 2 * ASTAGE)  // 98304 -> 2 CTAs/SM

typedef signed char s8;

__device__ s8 g_q1[(size_t)M_TOTAL * K_TOTAL];   // slice 1 of x
__device__ s8 g_q2[(size_t)M_TOTAL * K_TOTAL];   // slice 2 of x
__device__ s8 g_w8[(size_t)N_TOTAL * K_TOTAL];   // weights as int8
__device__ float g_rs[M_TOTAL];                  // rowsum(x)
__device__ float g_s [M_TOTAL];                  // s2 = s1/254 per row

#define CP16(sa, g) \
    asm volatile("cp.async.cg.shared.global [%0], [%1], 16;" :: "r"(sa), "l"(g))
#define CP_COMMIT() asm volatile("cp.async.commit_group;" ::: "memory")
#define CP_WAIT(n)  asm volatile("cp.async.wait_group %0;" :: "n"(n) : "memory")

#define LDSM4(r, addr) \
    asm volatile("ldmatrix.sync.aligned.m8n8.x4.shared.b16 {%0,%1,%2,%3}, [%4];" \
                 : "=r"((r)[0]), "=r"((r)[1]), "=r"((r)[2]), "=r"((r)[3]) \
                 : "r"(addr))

#define MMA_S8(d, a, b0, b1)                                                   \
    asm volatile("mma.sync.aligned.m16n8k32.row.col.s32.s8.s8.s32 "            \
                 "{%0,%1,%2,%3},{%4,%5,%6,%7},{%8,%9},{%0,%1,%2,%3};"          \
                 : "+r"((d)[0]), "+r"((d)[1]), "+r"((d)[2]), "+r"((d)[3])      \
                 : "r"((a)[0]), "r"((a)[1]), "r"((a)[2]), "r"((a)[3]),         \
                   "r"(b0), "r"(b1))

__device__ __forceinline__ uint32_t packq(int a, int b, int c, int d) {
    return (uint32_t)(a & 255) | ((uint32_t)(b & 255) << 8) |
           ((uint32_t)(c & 255) << 16) | ((uint32_t)(d & 255) << 24);
}

// ============================================================================
// Kernel 1: x -> two int8 slices + rowsum + per-row scale. One block per row.
// ============================================================================
__global__ void __launch_bounds__(256) prep_x(const float* __restrict__ x) {
    const int row = blockIdx.x;
    const int tid = threadIdx.x;
    const int lane = tid & 31;
    const int wid = tid >> 5;
    const float4* xr = reinterpret_cast<const float4*>(x + (size_t)row * K_TOTAL);

    float4 v[4];
    float mx = 0.f, sm = 0.f;
#pragma unroll
    for (int k = 0; k < 4; k++) {
        v[k] = xr[k * 256 + tid];
        mx = fmaxf(mx, fmaxf(fmaxf(fabsf(v[k].x), fabsf(v[k].y)),
                             fmaxf(fabsf(v[k].z), fabsf(v[k].w))));
        sm += (v[k].x + v[k].y) + (v[k].z + v[k].w);
    }
#pragma unroll
    for (int o = 16; o > 0; o >>= 1) {
        mx = fmaxf(mx, __shfl_xor_sync(0xffffffffu, mx, o));
        sm += __shfl_xor_sync(0xffffffffu, sm, o);
    }
    __shared__ float smx[8], ssm[8];
    if (lane == 0) { smx[wid] = mx; ssm[wid] = sm; }
    __syncthreads();
    mx = smx[0]; sm = ssm[0];
#pragma unroll
    for (int w = 1; w < 8; w++) { mx = fmaxf(mx, smx[w]); sm += ssm[w]; }

    float s1, inv1, inv2;
    if (mx < 1e-20f) { s1 = 0.f; inv1 = 0.f; inv2 = 0.f; }
    else { s1 = mx * (1.f / 127.f); inv1 = 127.f / mx; inv2 = inv1 * 254.f; }

    uint32_t* q1o = reinterpret_cast<uint32_t*>(g_q1) + (size_t)row * (K_TOTAL / 4);
    uint32_t* q2o = reinterpret_cast<uint32_t*>(g_q2) + (size_t)row * (K_TOTAL / 4);
#pragma unroll
    for (int k = 0; k < 4; k++) {
        const float f[4] = {v[k].x, v[k].y, v[k].z, v[k].w};
        int qa[4], qb[4];
#pragma unroll
        for (int j = 0; j < 4; j++) {
            int a = __float2int_rn(f[j] * inv1);
            a = max(-127, min(127, a));
            float r = fmaf(-s1, (float)a, f[j]);
            int b = __float2int_rn(r * inv2);
            b = max(-127, min(127, b));
            qa[j] = a; qb[j] = b;
        }
        q1o[k * 256 + tid] = packq(qa[0], qa[1], qa[2], qa[3]);
        q2o[k * 256 + tid] = packq(qb[0], qb[1], qb[2], qb[3]);
    }
    if (tid == 0) { g_rs[row] = sm; g_s[row] = s1 * (1.f / 254.f); }
}

// ============================================================================
// Kernel 2: weights fp32(int-valued) -> int8 (exact cast), packed.
// ============================================================================
__global__ void __launch_bounds__(256) prep_w(const float* __restrict__ w) {
    size_t i = (size_t)blockIdx.x * 256 + threadIdx.x;     // uint4 index
    const float4* s = reinterpret_cast<const float4*>(w) + i * 4;
    float4 a = s[0], b = s[1], c = s[2], d = s[3];
    uint4 o;
    o.x = packq((int)a.x, (int)a.y, (int)a.z, (int)a.w);
    o.y = packq((int)b.x, (int)b.y, (int)b.z, (int)b.w);
    o.z = packq((int)c.x, (int)c.y, (int)c.z, (int)c.w);
    o.w = packq((int)d.x, (int)d.y, (int)d.z, (int)d.w);
    reinterpret_cast<uint4*>(g_w8)[i] = o;
}

// ============================================================================
// Kernel 3: int8 GEMM. 128x128 tile, BK=128 bytes, 3-stage cp.async,
// XOR-swizzled 128B rows, ldmatrix frags (byte-identical addressing to R9).
// ============================================================================
__device__ __forceinline__ void load_tile(const s8* __restrict__ gA,
                                          const s8* __restrict__ gB,
                                          uint32_t sAst, uint32_t sBst,
                                          const uint32_t* soff, int cb, int kkb) {
#pragma unroll
    for (int i = 0; i < 4; i++) {
        CP16(sAst + soff[i], gA + kkb + (cb + i) * 16);
        CP16(sBst + soff[i], gB + kkb + (cb + i) * 16);
    }
}

__global__ void __launch_bounds__(256, 2) gemm_kernel(
    const float* __restrict__ scales, const float* __restrict__ zp,
    const float* __restrict__ bias, float* __restrict__ out) {
    extern __shared__ char smem[];
    const uint32_t sbase = (uint32_t)__cvta_generic_to_shared(smem);
    const int tid = threadIdx.x;
    const int lane = tid & 31;
    const int wid = tid >> 5;
    const int warp_m = wid >> 2;            // 0..1 (64 rows)
    const int warp_n = wid & 3;             // 0..3 (32 cols)
    const int m0 = blockIdx.y * BM;
    const int n0 = blockIdx.x * BN;

    // ---- loader: row = tid>>1, chunks cb..cb+3 (16B), swizzled ----
    const int lr = tid >> 1;
    const int cb = (tid & 1) * 4;
    const s8* gA1 = g_q1 + (size_t)(m0 + lr) * K_TOTAL;
    const s8* gA2 = g_q2 + (size_t)(m0 + lr) * K_TOTAL;
    const s8* gB  = g_w8 + (size_t)(n0 + lr) * K_TOTAL;
    uint32_t soff[4];
#pragma unroll
    for (int i = 0; i < 4; i++)
        soff[i] = (uint32_t)(lr * 128 + (((cb + i) ^ (lr & 7)) << 4));

    // ---- ldmatrix addressing (identical byte pattern to tf32 version) ----
    const uint32_t sa = lane & 7;
    const uint32_t c0a = lane >> 4;          // A chunk parity
    const uint32_t c0b = (lane >> 3) & 1;    // B chunk parity
    uint32_t aoff[4];
#pragma unroll
    for (int mt = 0; mt < 4; mt++) {
        int rowA = warp_m * 64 + mt * 16 + ((lane >> 3) & 1) * 8 + (lane & 7);
        aoff[mt] = (uint32_t)(rowA * 128);
    }
    uint32_t boff[2];
#pragma unroll
    for (int bg = 0; bg < 2; bg++) {
        int rowB = warp_n * 32 + bg * 16 + ((lane >> 4) & 1) * 8 + (lane & 7);
        boff[bg] = (uint32_t)(rowB * 128);
    }

    int acc[4][4][4];
#pragma unroll
    for (int i = 0; i < 4; i++)
#pragma unroll
        for (int j = 0; j < 4; j++)
#pragma unroll
            for (int k = 0; k < 4; k++) acc[i][j][k] = 0;

    // ---- prologue: fill 2 of 3 stages (both slice 1) ----
    load_tile(gA1, gB, sbase, sbase + NST * ASTAGE, soff, cb, 0);
    CP_COMMIT();
    load_tile(gA1, gB, sbase + ASTAGE, sbase + NST * ASTAGE + ASTAGE, soff, cb, BKB);
    CP_COMMIT();

    int sidx = 0;
    for (int it = 0; it < NITERS; it++) {
        CP_WAIT(1);
        __syncthreads();

        int nidx = sidx + 2; if (nidx >= NST) nidx -= NST;
        int nxt = it + 2;
        if (nxt < NITERS) {
            const s8* ga = (nxt < HALF_ITERS) ? gA1 : gA2;
            load_tile(ga, gB, sbase + nidx * ASTAGE,
                      sbase + NST * ASTAGE + nidx * ASTAGE, soff, cb,
                      (nxt & (HALF_ITERS - 1)) << 7);
        }
        CP_COMMIT();

        if (it == HALF_ITERS) {   // slice boundary: acc = 254*d1, then add d2
#pragma unroll
            for (int i = 0; i < 4; i++)
#pragma unroll
                for (int j = 0; j < 4; j++)
#pragma unroll
                    for (int k = 0; k < 4; k++) acc[i][j][k] *= 254;
        }

        const uint32_t Ab = sbase + sidx * ASTAGE;
        const uint32_t Bb = sbase + NST * ASTAGE + sidx * ASTAGE;
#pragma unroll
        for (int ks = 0; ks < 4; ks++) {   // 4 k32-slices per 128B row
            uint32_t a[4][4];
#pragma unroll
            for (int mt = 0; mt < 4; mt++)
                LDSM4(a[mt], Ab + aoff[mt] + ((((uint32_t)(2 * ks) + c0a) ^ sa) << 4));
            uint32_t b[2][4];
#pragma unroll
            for (int bg = 0; bg < 2; bg++)
                LDSM4(b[bg], Bb + boff[bg] + ((((uint32_t)(2 * ks) + c0b) ^ sa) << 4));
#pragma unroll
            for (int mt = 0; mt < 4; mt++)
#pragma unroll
                for (int nt = 0; nt < 4; nt++)
                    MMA_S8(acc[mt][nt], a[mt], b[nt >> 1][(nt & 1) * 2],
                           b[nt >> 1][(nt & 1) * 2 + 1]);
        }
        sidx++; if (sidx >= NST) sidx = 0;
    }

    // ---- epilogue: out = (s2[m]*acc)*scale - (scale*zp)*rowsum + bias ----
    const int g = lane >> 2;
    const int t = lane & 3;
    float sc[8], szp[8], bi[8];
#pragma unroll
    for (int nt = 0; nt < 4; nt++) {
#pragma unroll
        for (int q = 0; q < 2; q++) {
            int n = n0 + warp_n * 32 + nt * 8 + t * 2 + q;
            float s = __ldg(scales + n);
            sc[nt * 2 + q] = s;
            szp[nt * 2 + q] = s * __ldg(zp + n);
            bi[nt * 2 + q] = __ldg(bias + n);
        }
    }
#pragma unroll
    for (int mt = 0; mt < 4; mt++) {
#pragma unroll
        for (int h = 0; h < 2; h++) {
            int row = m0 + warp_m * 64 + mt * 16 + g + h * 8;
            float r = g_rs[row];
            float s2r = g_s[row];
#pragma unroll
            for (int nt = 0; nt < 4; nt++) {
                int col = n0 + warp_n * 32 + nt * 8 + t * 2;
                float f0 = (float)acc[mt][nt][h * 2 + 0] * s2r;
                float f1 = (float)acc[mt][nt][h * 2 + 1] * s2r;
                float2 v;
                v.x = fmaf(f0, sc[nt * 2 + 0], fmaf(-szp[nt * 2 + 0], r, bi[nt * 2 + 0]));
                v.y = fmaf(f1, sc[nt * 2 + 1], fmaf(-szp[nt * 2 + 1], r, bi[nt * 2 + 1]));
                *reinterpret_cast<float2*>(out + (size_t)row * N_TOTAL + col) = v;
            }
        }
    }
}

// ============================================================================
// Launch
// ============================================================================
extern "C" void kernel_launch(void* const* d_in, const int* in_sizes, int n_in,
                              void* d_out, int out_size) {
    const float* x      = (const float*)d_in[0];
    const float* wf     = (const float*)d_in[1];
    const float* scales = (const float*)d_in[2];
    const float* zp     = (const float*)d_in[3];
    const float* bias   = (const float*)d_in[4];
    float* out = (float*)d_out;

    prep_x<<<M_TOTAL, 256>>>(x);
    prep_w<<<(N_TOTAL / 16) * (K_TOTAL / 256), 256>>>(wf);

    cudaFuncSetAttribute(gemm_kernel, cudaFuncAttributeMaxDynamicSharedMemorySize,
                         SMEM_BYTES);
    dim3 grid(N_TOTAL / BN, M_TOTAL / BM, 1);   // n-fastest: W tiles L2-resident
    gemm_kernel<<<grid, 256, SMEM_BYTES>>>(scales, zp, bias, out);
}

// round 12
// speedup vs baseline: 2.1030x; 2.1030x over previous
#include <cuda_runtime.h>
#include <cstdint>

// ============================================================================
// out[16384,4096] = x @ ((W_int - zp)*scale)^T + bias       (sm_103, no tcgen05)
// tf32 mma.sync HMMA (int8 IMMA measured 4x slower per instr on sm_103 - R11).
// W ints exact in tf32 (raw f32 bits); x pre-rounded rna in prepass.
// CTA tile 128x256, 8 warps of 64x64 (0.172 B/MAC smem vs 0.25 in R9),
// 4-stage cp.async, XOR-swizzled 128B rows, ldmatrix frags.
// Epilogue: out = scale*G - (scale*zp)*rowsum(x) + bias.
// ============================================================================

#define M_TOTAL 16384
#define N_TOTAL 4096
#define K_TOTAL 4096
#define BM 128
#define BN 256
#define BK 32
#define NST 4
#define NITERS (K_TOTAL / BK)          // 128
#define ASTAGE 16384                   // A: 128 rows x 128B
#define BSTAGE 32768                   // B: 256 rows x 128B
#define STAGE_BYTES (ASTAGE + BSTAGE)  // 48KB
#define SMEM_BYTES (NST * STAGE_BYTES) // 196608 -> 1 CTA/SM

__device__ float g_xa[(size_t)M_TOTAL * K_TOTAL];   // tf32-rounded x
__device__ float g_rs[M_TOTAL];                     // per-row sum of x

#define CP16(sa, g) \
    asm volatile("cp.async.cg.shared.global [%0], [%1], 16;" :: "r"(sa), "l"(g))
#define CP_COMMIT() asm volatile("cp.async.commit_group;" ::: "memory")
#define CP_WAIT(n)  asm volatile("cp.async.wait_group %0;" :: "n"(n) : "memory")

__device__ __forceinline__ uint32_t f2tf32(float f) {
    uint32_t u;
    asm("cvt.rna.tf32.f32 %0, %1;" : "=r"(u) : "f"(f));
    return u;
}

#define LDSM4(r, addr) \
    asm volatile("ldmatrix.sync.aligned.m8n8.x4.shared.b16 {%0,%1,%2,%3}, [%4];" \
                 : "=r"((r)[0]), "=r"((r)[1]), "=r"((r)[2]), "=r"((r)[3]) \
                 : "r"(addr))

#define MMA_TF32(d, a, b0, b1)                                                 \
    asm volatile("mma.sync.aligned.m16n8k8.row.col.f32.tf32.tf32.f32 "         \
                 "{%0,%1,%2,%3},{%4,%5,%6,%7},{%8,%9},{%0,%1,%2,%3};"          \
                 : "+f"((d)[0]), "+f"((d)[1]), "+f"((d)[2]), "+f"((d)[3])      \
                 : "r"((a)[0]), "r"((a)[1]), "r"((a)[2]), "r"((a)[3]),         \
                   "r"(b0), "r"(b1))

// ============================================================================
// Kernel 1: x -> tf32-rounded copy + per-row sum. One warp per row.
// ============================================================================
__global__ void __launch_bounds__(256) prep_kernel(const float* __restrict__ x) {
    int row = blockIdx.x * 8 + (threadIdx.x >> 5);
    int lane = threadIdx.x & 31;
    const float4* xr = reinterpret_cast<const float4*>(x + (size_t)row * K_TOTAL);
    float4* xo = reinterpret_cast<float4*>(g_xa + (size_t)row * K_TOTAL);
    float s = 0.f;
#pragma unroll 4
    for (int i = lane; i < K_TOTAL / 4; i += 32) {
        float4 v = xr[i];
        s += (v.x + v.y) + (v.z + v.w);
        float4 o;
        o.x = __uint_as_float(f2tf32(v.x));
        o.y = __uint_as_float(f2tf32(v.y));
        o.z = __uint_as_float(f2tf32(v.z));
        o.w = __uint_as_float(f2tf32(v.w));
        xo[i] = o;
    }
#pragma unroll
    for (int o = 16; o > 0; o >>= 1) s += __shfl_xor_sync(0xffffffffu, s, o);
    if (lane == 0) g_rs[row] = s;
}

// ============================================================================
// Kernel 2: tf32 GEMM, 128x256x32 tile, 8 warps of 64x64, 4-stage pipeline.
// ============================================================================
__global__ void __launch_bounds__(256, 1) gemm_kernel(
    const float* __restrict__ w,
    const float* __restrict__ scales, const float* __restrict__ zp,
    const float* __restrict__ bias, float* __restrict__ out) {
    extern __shared__ float smem[];
    const uint32_t sbase = (uint32_t)__cvta_generic_to_shared(smem);
    const int tid = threadIdx.x;
    const int lane = tid & 31;
    const int wid = tid >> 5;
    const int warp_m = wid >> 2;            // 0..1 (64 rows)
    const int warp_n = wid & 3;             // 0..3 (64 cols)
    const int m0 = blockIdx.y * BM;
    const int n0 = blockIdx.x * BN;

    // ---- loader: A row lr (128), B rows lr and lr+128; 4 chunks each ----
    const int lr = tid >> 1;
    const int cb = (tid & 1) * 4;
    const float* gA  = g_xa + (size_t)(m0 + lr) * K_TOTAL;
    const float* gB0 = w + (size_t)(n0 + lr) * K_TOTAL;
    const float* gB1 = w + (size_t)(n0 + lr + 128) * K_TOTAL;
    uint32_t soff[4];
#pragma unroll
    for (int i = 0; i < 4; i++)
        soff[i] = (uint32_t)(lr * 128 + (((cb + i) ^ (lr & 7)) << 4));

    // ---- ldmatrix per-lane addressing (proven R9 pattern) ----
    const uint32_t sa = lane & 7;
    const uint32_t c0a = lane >> 4;          // A chunk parity
    const uint32_t c0b = (lane >> 3) & 1;    // B chunk parity
    uint32_t aoff[4];
#pragma unroll
    for (int mt = 0; mt < 4; mt++) {
        int rowA = warp_m * 64 + mt * 16 + ((lane >> 3) & 1) * 8 + (lane & 7);
        aoff[mt] = (uint32_t)(rowA * 128);
    }
    uint32_t boff[4];
#pragma unroll
    for (int bg = 0; bg < 4; bg++) {
        int rowB = warp_n * 64 + bg * 16 + ((lane >> 4) & 1) * 8 + (lane & 7);
        boff[bg] = (uint32_t)(rowB * 128);
    }

    float acc[4][8][4];                      // 128 regs: 64x64 warp tile
#pragma unroll
    for (int i = 0; i < 4; i++)
#pragma unroll
        for (int j = 0; j < 8; j++)
#pragma unroll
            for (int k = 0; k < 4; k++) acc[i][j][k] = 0.f;

    // ---- prologue: fill NST-1 stages ----
#pragma unroll
    for (int p = 0; p < NST - 1; p++) {
        uint32_t As = sbase + p * STAGE_BYTES;
        uint32_t Bs = As + ASTAGE;
        int kk = p * BK;
#pragma unroll
        for (int i = 0; i < 4; i++) {
            CP16(As + soff[i], gA + kk + (cb + i) * 4);
            CP16(Bs + soff[i], gB0 + kk + (cb + i) * 4);
            CP16(Bs + 16384u + soff[i], gB1 + kk + (cb + i) * 4);
        }
        CP_COMMIT();
    }

    int sidx = 0;
    for (int it = 0; it < NITERS; it++) {
        CP_WAIT(NST - 2);
        __syncthreads();

        int nidx = sidx + (NST - 1); if (nidx >= NST) nidx -= NST;
        int nxt = it + (NST - 1);
        if (nxt < NITERS) {
            uint32_t As = sbase + nidx * STAGE_BYTES;
            uint32_t Bs = As + ASTAGE;
            int kk = nxt * BK;
#pragma unroll
            for (int i = 0; i < 4; i++) {
                CP16(As + soff[i], gA + kk + (cb + i) * 4);
                CP16(Bs + soff[i], gB0 + kk + (cb + i) * 4);
                CP16(Bs + 16384u + soff[i], gB1 + kk + (cb + i) * 4);
            }
        }
        CP_COMMIT();

        const uint32_t Ab = sbase + sidx * STAGE_BYTES;
        const uint32_t Bb = Ab + ASTAGE;
#pragma unroll
        for (int ks = 0; ks < 4; ks++) {
            const uint32_t csw = (((uint32_t)(2 * ks) + c0a) ^ sa) << 4;
            const uint32_t cswb = (((uint32_t)(2 * ks) + c0b) ^ sa) << 4;
            uint32_t a[4][4];
#pragma unroll
            for (int mt = 0; mt < 4; mt++) LDSM4(a[mt], Ab + aoff[mt] + csw);
            uint32_t b[4][4];
#pragma unroll
            for (int bg = 0; bg < 4; bg++) LDSM4(b[bg], Bb + boff[bg] + cswb);
#pragma unroll
            for (int mt = 0; mt < 4; mt++)
#pragma unroll
                for (int nt = 0; nt < 8; nt++)
                    MMA_TF32(acc[mt][nt], a[mt], b[nt >> 1][(nt & 1) * 2],
                             b[nt >> 1][(nt & 1) * 2 + 1]);
        }
        sidx++; if (sidx >= NST) sidx = 0;
    }

    // ---- epilogue: out = acc*scale - (scale*zp)*rowsum + bias ----
    const int g = lane >> 2;
    const int t = lane & 3;
    float rs[8];
#pragma unroll
    for (int mt = 0; mt < 4; mt++) {
        rs[mt * 2 + 0] = g_rs[m0 + warp_m * 64 + mt * 16 + g];
        rs[mt * 2 + 1] = g_rs[m0 + warp_m * 64 + mt * 16 + g + 8];
    }
#pragma unroll
    for (int nt = 0; nt < 8; nt++) {
        int n = n0 + warp_n * 64 + nt * 8 + t * 2;
        float s0 = __ldg(scales + n),     s1 = __ldg(scales + n + 1);
        float z0 = s0 * __ldg(zp + n),    z1 = s1 * __ldg(zp + n + 1);
        float b0 = __ldg(bias + n),       b1 = __ldg(bias + n + 1);
#pragma unroll
        for (int mt = 0; mt < 4; mt++) {
#pragma unroll
            for (int h = 0; h < 2; h++) {
                int row = m0 + warp_m * 64 + mt * 16 + g + h * 8;
                float r = rs[mt * 2 + h];
                float2 v;
                v.x = fmaf(acc[mt][nt][h * 2 + 0], s0, fmaf(-z0, r, b0));
                v.y = fmaf(acc[mt][nt][h * 2 + 1], s1, fmaf(-z1, r, b1));
                *reinterpret_cast<float2*>(out + (size_t)row * N_TOTAL + n) = v;
            }
        }
    }
}

// ============================================================================
// Launch
// ============================================================================
extern "C" void kernel_launch(void* const* d_in, const int* in_sizes, int n_in,
                              void* d_out, int out_size) {
    const float* x      = (const float*)d_in[0];
    const float* wf     = (const float*)d_in[1];
    const float* scales = (const float*)d_in[2];
    const float* zp     = (const float*)d_in[3];
    const float* bias   = (const float*)d_in[4];
    float* out = (float*)d_out;

    prep_kernel<<<M_TOTAL / 8, 256>>>(x);

    cudaFuncSetAttribute(gemm_kernel, cudaFuncAttributeMaxDynamicSharedMemorySize,
                         SMEM_BYTES);
    dim3 grid(N_TOTAL / BN, M_TOTAL / BM, 1);   // n-fastest: W slab L2-resident
    gemm_kernel<<<grid, 256, SMEM_BYTES>>>(wf, scales, zp, bias, out);
}

// round 13
// speedup vs baseline: 2.1101x; 1.0034x over previous
#include <cuda_runtime.h>
#include <cstdint>

// ============================================================================
// out[16384,4096] = x @ ((W_int - zp)*scale)^T + bias       (sm_103, no tcgen05)
// tf32 mma.sync HMMA. W ints exact in tf32 (raw f32 bits); x pre-rounded (rna).
// CTA tile 128x256, 8 warps of 64x64 (0.172 B/MAC). 4-stage cp.async.
// R13 changes vs R12: fragment double-buffering (LDSM ks+1 ahead of MMA ks),
// cp.async issue moved after phase-0 LDSM -> MMAs start immediately post-sync.
// Epilogue: out = scale*G - (scale*zp)*rowsum(x) + bias.
// ============================================================================

#define M_TOTAL 16384
#define N_TOTAL 4096
#define K_TOTAL 4096
#define BM 128
#define BN 256
#define BK 32
#define NST 4
#define NITERS (K_TOTAL / BK)          // 128
#define ASTAGE 16384                   // A: 128 rows x 128B
#define BSTAGE 32768                   // B: 256 rows x 128B
#define STAGE_BYTES (ASTAGE + BSTAGE)  // 48KB
#define SMEM_BYTES (NST * STAGE_BYTES) // 196608 -> 1 CTA/SM

__device__ float g_xa[(size_t)M_TOTAL * K_TOTAL];   // tf32-rounded x
__device__ float g_rs[M_TOTAL];                     // per-row sum of x

#define CP16(sa, g) \
    asm volatile("cp.async.cg.shared.global [%0], [%1], 16;" :: "r"(sa), "l"(g))
#define CP_COMMIT() asm volatile("cp.async.commit_group;" ::: "memory")
#define CP_WAIT(n)  asm volatile("cp.async.wait_group %0;" :: "n"(n) : "memory")

__device__ __forceinline__ uint32_t f2tf32(float f) {
    uint32_t u;
    asm("cvt.rna.tf32.f32 %0, %1;" : "=r"(u) : "f"(f));
    return u;
}

#define LDSM4(r, addr) \
    asm volatile("ldmatrix.sync.aligned.m8n8.x4.shared.b16 {%0,%1,%2,%3}, [%4];" \
                 : "=r"((r)[0]), "=r"((r)[1]), "=r"((r)[2]), "=r"((r)[3]) \
                 : "r"(addr))

#define MMA_TF32(d, a, b0, b1)                                                 \
    asm volatile("mma.sync.aligned.m16n8k8.row.col.f32.tf32.tf32.f32 "         \
                 "{%0,%1,%2,%3},{%4,%5,%6,%7},{%8,%9},{%0,%1,%2,%3};"          \
                 : "+f"((d)[0]), "+f"((d)[1]), "+f"((d)[2]), "+f"((d)[3])      \
                 : "r"((a)[0]), "r"((a)[1]), "r"((a)[2]), "r"((a)[3]),         \
                   "r"(b0), "r"(b1))

// ============================================================================
// Kernel 1: x -> tf32-rounded copy + per-row sum. One warp per row.
// ============================================================================
__global__ void __launch_bounds__(256) prep_kernel(const float* __restrict__ x) {
    int row = blockIdx.x * 8 + (threadIdx.x >> 5);
    int lane = threadIdx.x & 31;
    const float4* xr = reinterpret_cast<const float4*>(x + (size_t)row * K_TOTAL);
    float4* xo = reinterpret_cast<float4*>(g_xa + (size_t)row * K_TOTAL);
    float s = 0.f;
#pragma unroll 4
    for (int i = lane; i < K_TOTAL / 4; i += 32) {
        float4 v = xr[i];
        s += (v.x + v.y) + (v.z + v.w);
        float4 o;
        o.x = __uint_as_float(f2tf32(v.x));
        o.y = __uint_as_float(f2tf32(v.y));
        o.z = __uint_as_float(f2tf32(v.z));
        o.w = __uint_as_float(f2tf32(v.w));
        xo[i] = o;
    }
#pragma unroll
    for (int o = 16; o > 0; o >>= 1) s += __shfl_xor_sync(0xffffffffu, s, o);
    if (lane == 0) g_rs[row] = s;
}

// ============================================================================
// Kernel 2: tf32 GEMM, 128x256x32 tile, 8 warps of 64x64, 4-stage pipeline,
// double-buffered register fragments.
// ============================================================================
__global__ void __launch_bounds__(256, 1) gemm_kernel(
    const float* __restrict__ w,
    const float* __restrict__ scales, const float* __restrict__ zp,
    const float* __restrict__ bias, float* __restrict__ out) {
    extern __shared__ float smem[];
    const uint32_t sbase = (uint32_t)__cvta_generic_to_shared(smem);
    const int tid = threadIdx.x;
    const int lane = tid & 31;
    const int wid = tid >> 5;
    const int warp_m = wid >> 2;            // 0..1 (64 rows)
    const int warp_n = wid & 3;             // 0..3 (64 cols)
    const int m0 = blockIdx.y * BM;
    const int n0 = blockIdx.x * BN;

    // ---- loader: A row lr (128), B rows lr and lr+128; 4 chunks each ----
    const int lr = tid >> 1;
    const int cb = (tid & 1) * 4;
    const float* gA  = g_xa + (size_t)(m0 + lr) * K_TOTAL;
    const float* gB0 = w + (size_t)(n0 + lr) * K_TOTAL;
    const float* gB1 = w + (size_t)(n0 + lr + 128) * K_TOTAL;
    uint32_t soff[4];
#pragma unroll
    for (int i = 0; i < 4; i++)
        soff[i] = (uint32_t)(lr * 128 + (((cb + i) ^ (lr & 7)) << 4));

    // ---- ldmatrix per-lane addressing (proven R9 pattern) ----
    const uint32_t sa = lane & 7;
    const uint32_t c0a = lane >> 4;          // A chunk parity
    const uint32_t c0b = (lane >> 3) & 1;    // B chunk parity
    uint32_t aoff[4];
#pragma unroll
    for (int mt = 0; mt < 4; mt++) {
        int rowA = warp_m * 64 + mt * 16 + ((lane >> 3) & 1) * 8 + (lane & 7);
        aoff[mt] = (uint32_t)(rowA * 128);
    }
    uint32_t boff[4];
#pragma unroll
    for (int bg = 0; bg < 4; bg++) {
        int rowB = warp_n * 64 + bg * 16 + ((lane >> 4) & 1) * 8 + (lane & 7);
        boff[bg] = (uint32_t)(rowB * 128);
    }

    float acc[4][8][4];                      // 128 regs: 64x64 warp tile
#pragma unroll
    for (int i = 0; i < 4; i++)
#pragma unroll
        for (int j = 0; j < 8; j++)
#pragma unroll
            for (int k = 0; k < 4; k++) acc[i][j][k] = 0.f;

    // ---- prologue: fill NST-1 stages ----
#pragma unroll
    for (int p = 0; p < NST - 1; p++) {
        uint32_t As = sbase + p * STAGE_BYTES;
        uint32_t Bs = As + ASTAGE;
        int kk = p * BK;
#pragma unroll
        for (int i = 0; i < 4; i++) {
            CP16(As + soff[i], gA + kk + (cb + i) * 4);
            CP16(Bs + soff[i], gB0 + kk + (cb + i) * 4);
            CP16(Bs + 16384u + soff[i], gB1 + kk + (cb + i) * 4);
        }
        CP_COMMIT();
    }

    uint32_t a[2][4][4], b[2][4][4];         // double-buffered fragments

    int sidx = 0;
    for (int it = 0; it < NITERS; it++) {
        CP_WAIT(NST - 2);
        __syncthreads();

        const uint32_t Ab = sbase + sidx * STAGE_BYTES;
        const uint32_t Bb = Ab + ASTAGE;

        // phase-0 fragments first: MMAs can start immediately
        {
            const uint32_t csw  = (c0a ^ sa) << 4;
            const uint32_t cswb = (c0b ^ sa) << 4;
#pragma unroll
            for (int mt = 0; mt < 4; mt++) LDSM4(a[0][mt], Ab + aoff[mt] + csw);
#pragma unroll
            for (int bg = 0; bg < 4; bg++) LDSM4(b[0][bg], Bb + boff[bg] + cswb);
        }

        // now issue next-stage loads (latency budget: 3 stages)
        int nidx = sidx + (NST - 1); if (nidx >= NST) nidx -= NST;
        int nxt = it + (NST - 1);
        if (nxt < NITERS) {
            uint32_t As = sbase + nidx * STAGE_BYTES;
            uint32_t Bs = As + ASTAGE;
            int kk = nxt * BK;
#pragma unroll
            for (int i = 0; i < 4; i++) {
                CP16(As + soff[i], gA + kk + (cb + i) * 4);
                CP16(Bs + soff[i], gB0 + kk + (cb + i) * 4);
                CP16(Bs + 16384u + soff[i], gB1 + kk + (cb + i) * 4);
            }
        }
        CP_COMMIT();

#pragma unroll
        for (int ks = 0; ks < 4; ks++) {
            const int cur = ks & 1;
            if (ks < 3) {                    // prefetch phase ks+1 fragments
                const uint32_t csw  = (((uint32_t)(2 * (ks + 1)) + c0a) ^ sa) << 4;
                const uint32_t cswb = (((uint32_t)(2 * (ks + 1)) + c0b) ^ sa) << 4;
#pragma unroll
                for (int mt = 0; mt < 4; mt++)
                    LDSM4(a[cur ^ 1][mt], Ab + aoff[mt] + csw);
#pragma unroll
                for (int bg = 0; bg < 4; bg++)
                    LDSM4(b[cur ^ 1][bg], Bb + boff[bg] + cswb);
            }
#pragma unroll
            for (int mt = 0; mt < 4; mt++)
#pragma unroll
                for (int nt = 0; nt < 8; nt++)
                    MMA_TF32(acc[mt][nt], a[cur][mt], b[cur][nt >> 1][(nt & 1) * 2],
                             b[cur][nt >> 1][(nt & 1) * 2 + 1]);
        }
        sidx++; if (sidx >= NST) sidx = 0;
    }

    // ---- epilogue: out = acc*scale - (scale*zp)*rowsum + bias ----
    const int g = lane >> 2;
    const int t = lane & 3;
    float rs[8];
#pragma unroll
    for (int mt = 0; mt < 4; mt++) {
        rs[mt * 2 + 0] = g_rs[m0 + warp_m * 64 + mt * 16 + g];
        rs[mt * 2 + 1] = g_rs[m0 + warp_m * 64 + mt * 16 + g + 8];
    }
#pragma unroll
    for (int nt = 0; nt < 8; nt++) {
        int n = n0 + warp_n * 64 + nt * 8 + t * 2;
        float s0 = __ldg(scales + n),     s1 = __ldg(scales + n + 1);
        float z0 = s0 * __ldg(zp + n),    z1 = s1 * __ldg(zp + n + 1);
        float b0 = __ldg(bias + n),       b1 = __ldg(bias + n + 1);
#pragma unroll
        for (int mt = 0; mt < 4; mt++) {
#pragma unroll
            for (int h = 0; h < 2; h++) {
                int row = m0 + warp_m * 64 + mt * 16 + g + h * 8;
                float r = rs[mt * 2 + h];
                float2 v;
                v.x = fmaf(acc[mt][nt][h * 2 + 0], s0, fmaf(-z0, r, b0));
                v.y = fmaf(acc[mt][nt][h * 2 + 1], s1, fmaf(-z1, r, b1));
                *reinterpret_cast<float2*>(out + (size_t)row * N_TOTAL + n) = v;
            }
        }
    }
}

// ============================================================================
// Launch
// ============================================================================
extern "C" void kernel_launch(void* const* d_in, const int* in_sizes, int n_in,
                              void* d_out, int out_size) {
    const float* x      = (const float*)d_in[0];
    const float* wf     = (const float*)d_in[1];
    const float* scales = (const float*)d_in[2];
    const float* zp     = (const float*)d_in[3];
    const float* bias   = (const float*)d_in[4];
    float* out = (float*)d_out;

    prep_kernel<<<M_TOTAL / 8, 256>>>(x);

    cudaFuncSetAttribute(gemm_kernel, cudaFuncAttributeMaxDynamicSharedMemorySize,
                         SMEM_BYTES);
    dim3 grid(N_TOTAL / BN, M_TOTAL / BM, 1);   // n-fastest: W slab L2-resident
    gemm_kernel<<<grid, 256, SMEM_BYTES>>>(wf, scales, zp, bias, out);
}